// round 5
// baseline (speedup 1.0000x reference)
#include <cuda_runtime.h>
#include <math.h>
#include <float.h>
#include <stdint.h>

#define BB 4
#define NN 4096
#define LL 256
#define KSEL 20
#define EPSF 1e-6f

// ---------------- scratch (static device globals; no allocation) ----------------
__device__ float2 g_xpair[(size_t)BB * NN * LL];         // interleaved (tf32 hi, lo residual)
__device__ float g_sim[(size_t)BB * NN * NN];            // 256 MB similarity matrix
__device__ uint32_t g_maskbits[BB * (NN / 32)];          // column mask as bits

// ---------------- kernel 0: mask -> bitmask ----------------
__global__ void kmask(const int* __restrict__ mask) {
    int b = blockIdx.x;
    int t = threadIdx.x;            // 0..127
    uint32_t w = 0;
#pragma unroll
    for (int q = 0; q < 32; q++)
        w |= (mask[b * NN + t * 32 + q] != 0 ? 1u : 0u) << q;
    g_maskbits[b * (NN / 32) + t] = w;
}

// ---------------- kernel 1: per-row normalization + tf32 hi/lo pair split --------
__global__ __launch_bounds__(128) void knorm(const float* __restrict__ hist,
                                             const int* __restrict__ mask) {
    int row = blockIdx.x * 4 + (threadIdx.x >> 5);
    if (row >= BB * NN) return;
    int lane = threadIdx.x & 31;
    const float* x = hist + (size_t)row * LL;

    float v[8];
#pragma unroll
    for (int i = 0; i < 2; i++) {
        float4 t = ((const float4*)x)[lane + i * 32];
        v[i * 4 + 0] = t.x; v[i * 4 + 1] = t.y; v[i * 4 + 2] = t.z; v[i * 4 + 3] = t.w;
    }
    float s = 0.f;
#pragma unroll
    for (int i = 0; i < 8; i++) s += v[i];
#pragma unroll
    for (int off = 16; off; off >>= 1) s += __shfl_xor_sync(0xffffffffu, s, off);
    float mean = s * (1.f / LL);

    float ss = 0.f;
#pragma unroll
    for (int i = 0; i < 8; i++) { float d = v[i] - mean; ss += d * d; }
#pragma unroll
    for (int off = 16; off; off >>= 1) ss += __shfl_xor_sync(0xffffffffu, ss, off);

    float denom = fmaxf(sqrtf(ss * (1.f / LL)), EPSF);
    float scale = (mask[row] != 0 ? 1.f : 0.f) / denom;

    float4* op = (float4*)(g_xpair + (size_t)row * LL);   // 2 pairs per float4
#pragma unroll
    for (int i = 0; i < 2; i++) {
        int e0 = 4 * (lane + i * 32);                     // first element of this quad
        float hi[4], lo[4];
#pragma unroll
        for (int q = 0; q < 4; q++) {
            float y = (v[i * 4 + q] - mean) * scale;
            unsigned uhi;
            asm("cvt.rna.tf32.f32 %0, %1;" : "=r"(uhi) : "f"(y));
            hi[q] = __uint_as_float(uhi);
            float r = y - hi[q];                          // exact
            unsigned ulo;
            asm("cvt.rna.tf32.f32 %0, %1;" : "=r"(ulo) : "f"(r));
            lo[q] = __uint_as_float(ulo);
        }
        float4 p0 = {hi[0], lo[0], hi[1], lo[1]};
        float4 p1 = {hi[2], lo[2], hi[3], lo[3]};
        op[e0 / 2]     = p0;
        op[e0 / 2 + 1] = p1;
    }
}

// ---------------- kernel 2: 3xTF32 GEMM, pair-smem, 3-stage, upper tiles --------
#define BM 128
#define BN 128
#define BK 16
#define NSTAGE 3
#define NKB (LL / BK)                    // 16
#define NTILE (NN / BM)                  // 32
#define NUPPER (NTILE * (NTILE + 1) / 2) // 528
#define TSTRIDE 132
#define STAGEF2 (BM * BK)                // 2048 float2 per stage per matrix

__device__ __forceinline__ void mma_tf32(float* d, const float* a, const float* b) {
    asm volatile(
        "mma.sync.aligned.m16n8k8.row.col.f32.tf32.tf32.f32 "
        "{%0,%1,%2,%3}, {%4,%5,%6,%7}, {%8,%9}, {%0,%1,%2,%3};"
        : "+f"(d[0]), "+f"(d[1]), "+f"(d[2]), "+f"(d[3])
        : "r"(__float_as_uint(a[0])), "r"(__float_as_uint(a[1])),
          "r"(__float_as_uint(a[2])), "r"(__float_as_uint(a[3])),
          "r"(__float_as_uint(b[0])), "r"(__float_as_uint(b[1])));
}

#define CPA16(dst32, src) \
    asm volatile("cp.async.cg.shared.global [%0], [%1], 16;\n" :: "r"(dst32), "l"(src))

// element (r,k) of a stage: float2 index r*16 + ((k>>1)^(r&7))*2 + (k&1)
__device__ __forceinline__ int sidx(int r, int k) {
    return r * 16 + (((k >> 1) ^ (r & 7)) * 2) + (k & 1);
}

__global__ __launch_bounds__(256, 2) void kgemm() {
    extern __shared__ float smem[];
    float2* As2 = (float2*)smem;                        // 3 stages x 16 KB
    float2* Bs2 = (float2*)(smem + 12288);              // 3 stages x 16 KB
    float* smem_t = smem;                               // reused for transpose

    // map linear tile id -> (ti, tj) upper triangular (tj >= ti)
    int t = blockIdx.x;
    int ti = 0;
    while (t >= NTILE - ti) { t -= NTILE - ti; ti++; }
    int tj = ti + t;

    int b = blockIdx.z;
    int tileM = ti * BM;
    int tileN = tj * BN;
    const float2* __restrict__ Xp = g_xpair + (size_t)b * NN * LL;
    float* __restrict__ C = g_sim + (size_t)b * NN * NN;

    int tid = threadIdx.x;
    int wid = tid >> 5;
    int lane = tid & 31;
    int g = lane >> 2;
    int tg = lane & 3;
    int m0w = (wid & 1) * 64;
    int n0w = (wid >> 1) * 32;

    // loader: 256 threads -> 128 rows x 2 halves of 4 16B-groups
    int lm = tid >> 1;
    int lq0 = (tid & 1) * 4;
    const float2* gA = Xp + (size_t)(tileM + lm) * LL;
    const float2* gB = Xp + (size_t)(tileN + lm) * LL;
    uint32_t base = (uint32_t)__cvta_generic_to_shared(smem);
    uint32_t sA = base + lm * 128;
    uint32_t sB = base + 49152 + lm * 128;
    int msw = lm & 7;

    float acc[4][4][4];
#pragma unroll
    for (int i = 0; i < 4; i++)
#pragma unroll
        for (int j = 0; j < 4; j++)
#pragma unroll
            for (int q = 0; q < 4; q++) acc[i][j][q] = 0.f;

    // prologue: stages 0,1
#pragma unroll
    for (int ps = 0; ps < 2; ps++) {
        const float2* pA = gA + ps * BK;
        const float2* pB = gB + ps * BK;
        uint32_t off = ps * 16384;
#pragma unroll
        for (int c = 0; c < 4; c++) {
            int q = lq0 + c;
            int sg = q ^ msw;
            CPA16(sA + off + sg * 16, pA + q * 2);
            CPA16(sB + off + sg * 16, pB + q * 2);
        }
        asm volatile("cp.async.commit_group;");
    }

    for (int kb = 0; kb < NKB; kb++) {
        asm volatile("cp.async.wait_group 1;");
        __syncthreads();

        if (kb + 2 < NKB) {
            int s = (kb + 2) % NSTAGE;
            const float2* pA = gA + (kb + 2) * BK;
            const float2* pB = gB + (kb + 2) * BK;
            uint32_t off = s * 16384;
#pragma unroll
            for (int c = 0; c < 4; c++) {
                int q = lq0 + c;
                int sg = q ^ msw;
                CPA16(sA + off + sg * 16, pA + q * 2);
                CPA16(sB + off + sg * 16, pB + q * 2);
            }
        }
        asm volatile("cp.async.commit_group;");

        const float2* Ast = As2 + (kb % NSTAGE) * STAGEF2;
        const float2* Bst = Bs2 + (kb % NSTAGE) * STAGEF2;
#pragma unroll
        for (int ks = 0; ks < 2; ks++) {
            int k1 = 8 * ks + tg;
            int k2 = k1 + 4;
            float bh[4][2], bl[4][2];
#pragma unroll
            for (int j = 0; j < 4; j++) {
                int nb = n0w + j * 8 + g;
                float2 t0 = Bst[sidx(nb, k1)];
                float2 t1 = Bst[sidx(nb, k2)];
                bh[j][0] = t0.x; bl[j][0] = t0.y;
                bh[j][1] = t1.x; bl[j][1] = t1.y;
            }
#pragma unroll
            for (int i = 0; i < 4; i++) {
                int r0 = m0w + i * 16 + g;
                int r1 = r0 + 8;
                float2 a00 = Ast[sidx(r0, k1)];
                float2 a10 = Ast[sidx(r1, k1)];
                float2 a01 = Ast[sidx(r0, k2)];
                float2 a11 = Ast[sidx(r1, k2)];
                float ah[4] = {a00.x, a10.x, a01.x, a11.x};
                float al[4] = {a00.y, a10.y, a01.y, a11.y};
#pragma unroll
                for (int j = 0; j < 4; j++) {
                    mma_tf32(acc[i][j], ah, bh[j]);       // hi*hi
                    mma_tf32(acc[i][j], ah, bl[j]);       // hi*lo
                    mma_tf32(acc[i][j], al, bh[j]);       // lo*hi
                }
            }
        }
    }

    // epilogue: scale, relu, zero-diag, store
    const float inv_l = 1.f / LL;
#pragma unroll
    for (int i = 0; i < 4; i++) {
        int gm0 = tileM + m0w + i * 16 + g;
        int gm1 = gm0 + 8;
#pragma unroll
        for (int j = 0; j < 4; j++) {
            int gn = tileN + n0w + j * 8 + 2 * tg;
            float v0 = fmaxf(acc[i][j][0] * inv_l, 0.f);
            float v1 = fmaxf(acc[i][j][1] * inv_l, 0.f);
            float v2 = fmaxf(acc[i][j][2] * inv_l, 0.f);
            float v3 = fmaxf(acc[i][j][3] * inv_l, 0.f);
            if (gm0 == gn)     v0 = 0.f;
            if (gm0 == gn + 1) v1 = 0.f;
            if (gm1 == gn)     v2 = 0.f;
            if (gm1 == gn + 1) v3 = 0.f;
            acc[i][j][0] = v0; acc[i][j][1] = v1;
            acc[i][j][2] = v2; acc[i][j][3] = v3;
            float2 r0 = {v0, v1}, r1 = {v2, v3};
            *(float2*)(C + (size_t)gm0 * NN + gn) = r0;
            *(float2*)(C + (size_t)gm1 * NN + gn) = r1;
        }
    }

    // mirror tile via smem transpose (off-diagonal only)
    if (ti != tj) {
        __syncthreads();   // all warps done reading stage buffers
#pragma unroll
        for (int i = 0; i < 4; i++) {
            int ml0 = m0w + i * 16 + g;
            int ml1 = ml0 + 8;
#pragma unroll
            for (int j = 0; j < 4; j++) {
                int nl = n0w + j * 8 + 2 * tg;
                smem_t[(nl)     * TSTRIDE + ml0] = acc[i][j][0];
                smem_t[(nl + 1) * TSTRIDE + ml0] = acc[i][j][1];
                smem_t[(nl)     * TSTRIDE + ml1] = acc[i][j][2];
                smem_t[(nl + 1) * TSTRIDE + ml1] = acc[i][j][3];
            }
        }
        __syncthreads();
#pragma unroll
        for (int it = 0; it < 16; it++) {
            int idx = it * 256 + tid;
            int r = idx >> 5;
            int c4 = idx & 31;
            float4 v = *(const float4*)&smem_t[r * TSTRIDE + c4 * 4];
            *(float4*)(C + (size_t)(tileN + r) * NN + tileM + c4 * 4) = v;
        }
    }
}

// ---------------- kernel 3: fused-load tournament top-20 + normalize ------------
#define TPB3 128
__global__ __launch_bounds__(TPB3) void ktopk(float* __restrict__ out) {
    int b = blockIdx.y;
    int row = blockIdx.x;
    const float* simrow = g_sim + ((size_t)b * NN + row) * NN;
    float* orow = out + ((size_t)b * NN + row) * NN;
    const uint32_t* mbits = g_maskbits + b * (NN / 32);

    __shared__ float sv[NN];
    __shared__ float cv[TPB3];
    __shared__ int   ci[TPB3];
    __shared__ float sel_v[KSEL];
    __shared__ int   sel_i[KSEL];
    __shared__ float fscale;

    int tid = threadIdx.x;
    int lane = tid & 31;

    // masked load + per-thread chunk max in one pass
    // thread t's chunk = elements {4t + 512j + e}, j=0..7, e=0..3 (ascending order)
    {
        float bv = -INFINITY; int bi = 0x7fffffff;
#pragma unroll
        for (int j = 0; j < 8; j++) {
            int i = tid * 4 + 512 * j;
            float4 v = *(const float4*)(simrow + i);
            uint32_t mb = (mbits[i >> 5] >> (i & 31)) & 0xFu;
            if (!(mb & 1u)) v.x = -FLT_MAX;
            if (!(mb & 2u)) v.y = -FLT_MAX;
            if (!(mb & 4u)) v.z = -FLT_MAX;
            if (!(mb & 8u)) v.w = -FLT_MAX;
            *(float4*)(sv + i) = v;
            if (v.x > bv) { bv = v.x; bi = i; }
            if (v.y > bv) { bv = v.y; bi = i + 1; }
            if (v.z > bv) { bv = v.z; bi = i + 2; }
            if (v.w > bv) { bv = v.w; bi = i + 3; }
        }
        cv[tid] = bv; ci[tid] = bi;
    }
    __syncthreads();

    if (tid < 32) {
        for (int it = 0; it < KSEL; it++) {
            float bv = cv[lane]; int bi = ci[lane];
#pragma unroll
            for (int t2 = 1; t2 < 4; t2++) {
                float v = cv[lane + 32 * t2]; int i2 = ci[lane + 32 * t2];
                if (v > bv || (v == bv && i2 < bi)) { bv = v; bi = i2; }
            }
#pragma unroll
            for (int off = 16; off; off >>= 1) {
                float ov = __shfl_xor_sync(0xffffffffu, bv, off);
                int   oi = __shfl_xor_sync(0xffffffffu, bi, off);
                if (ov > bv || (ov == bv && oi < bi)) { bv = ov; bi = oi; }
            }
            if (lane == 0) {
                sel_v[it] = bv;
                sel_i[it] = bi;
                sv[bi] = -INFINITY;
            }
            __syncwarp();
            // rescan the evicted winner's chunk
            int c = (bi >> 2) & (TPB3 - 1);
            int idx = 4 * c + 512 * (lane >> 2) + (lane & 3);
            float nv = sv[idx]; int ni = idx;
#pragma unroll
            for (int off = 16; off; off >>= 1) {
                float ov = __shfl_xor_sync(0xffffffffu, nv, off);
                int   oi = __shfl_xor_sync(0xffffffffu, ni, off);
                if (ov > nv || (ov == nv && oi < ni)) { nv = ov; ni = oi; }
            }
            if (lane == 0) { cv[c] = nv; ci[c] = ni; }
            __syncwarp();
        }
        if (lane == 0) {
            float S = 0.f;
#pragma unroll
            for (int t2 = 0; t2 < KSEL; t2++) {
                float v = sel_v[t2];
                if (v < 0.f) v = 0.f;            // masked / negative -> 0
                if (sel_i[t2] == row) v = 0.f;   // diagonal excluded
                sel_v[t2] = v;
                S += v;
            }
            float r1 = 1.f / fmaxf(S, EPSF);
            float S1 = S * r1;
            float r2 = 1.f / fmaxf(S1, EPSF);
            fscale = r1 * r2;
        }
    }
    __syncthreads();

    // zero the output row directly, then scatter the 20 normalized values
    float4 z = {0.f, 0.f, 0.f, 0.f};
#pragma unroll
    for (int j = 0; j < 8; j++)
        *(float4*)(orow + tid * 4 + 512 * j) = z;
    __syncthreads();
    if (tid < KSEL) orow[sel_i[tid]] = sel_v[tid] * fscale;
}

// ---------------- launch ----------------
extern "C" void kernel_launch(void* const* d_in, const int* in_sizes, int n_in,
                              void* d_out, int out_size) {
    const float* hist = (const float*)d_in[0];
    const int* mask = (const int*)d_in[1];
    float* out = (float*)d_out;

    static int smem_set = 0;
    if (!smem_set) {
        cudaFuncSetAttribute(kgemm, cudaFuncAttributeMaxDynamicSharedMemorySize,
                             98304);
        smem_set = 1;
    }

    kmask<<<BB, NN / 32>>>(mask);
    knorm<<<(BB * NN) / 4, 128>>>(hist, mask);

    dim3 g2(NUPPER, 1, BB);
    kgemm<<<g2, 256, 98304>>>();

    dim3 g3(NN, BB);
    ktopk<<<g3, TPB3>>>(out);
}

// round 8
// speedup vs baseline: 1.6940x; 1.6940x over previous
#include <cuda_runtime.h>
#include <cuda_fp16.h>
#include <math.h>
#include <float.h>
#include <stdint.h>

#define BB 4
#define NN 4096
#define LL 256
#define KSEL 20
#define EPSF 1e-6f

// ---------------- scratch (static device globals; no allocation) ----------------
// fp16 hi/lo planes, stored as u32 (fp16x2 pairs) in k-permuted dslot order:
// per 32-k chunk (16 u32): u32 position = 2*(4*ks + tg) + hs holds k-pair
// q = 8*ks + tg + 4*hs  (pair q covers k = 2q, 2q+1), ks,hs in {0,1}, tg in 0..3.
__device__ uint32_t g_hi[(size_t)BB * NN * 128];
__device__ uint32_t g_lo[(size_t)BB * NN * 128];
__device__ float g_sim[(size_t)BB * NN * NN];            // 256 MB similarity
__device__ uint32_t g_maskbits[BB * (NN / 32)];          // column mask bits

// ---------------- kernel 0: mask -> bitmask ----------------
__global__ void kmask(const int* __restrict__ mask) {
    int b = blockIdx.x;
    int t = threadIdx.x;
    uint32_t w = 0;
#pragma unroll
    for (int q = 0; q < 32; q++)
        w |= (mask[b * NN + t * 32 + q] != 0 ? 1u : 0u) << q;
    g_maskbits[b * (NN / 32) + t] = w;
}

// ---------------- kernel 1: per-row normalization + fp16 hi/lo split ------------
__global__ __launch_bounds__(128) void knorm(const float* __restrict__ hist,
                                             const int* __restrict__ mask) {
    int row = blockIdx.x * 4 + (threadIdx.x >> 5);
    if (row >= BB * NN) return;
    int lane = threadIdx.x & 31;
    const float* x = hist + (size_t)row * LL;

    float v[8];
#pragma unroll
    for (int i = 0; i < 2; i++) {
        float4 t = ((const float4*)x)[lane + i * 32];
        v[i * 4 + 0] = t.x; v[i * 4 + 1] = t.y; v[i * 4 + 2] = t.z; v[i * 4 + 3] = t.w;
    }
    float s = 0.f;
#pragma unroll
    for (int i = 0; i < 8; i++) s += v[i];
#pragma unroll
    for (int off = 16; off; off >>= 1) s += __shfl_xor_sync(0xffffffffu, s, off);
    float mean = s * (1.f / LL);

    float ss = 0.f;
#pragma unroll
    for (int i = 0; i < 8; i++) { float d = v[i] - mean; ss += d * d; }
#pragma unroll
    for (int off = 16; off; off >>= 1) ss += __shfl_xor_sync(0xffffffffu, ss, off);

    float denom = fmaxf(sqrtf(ss * (1.f / LL)), EPSF);
    float scale = (mask[row] != 0 ? 1.f : 0.f) / denom;

    uint32_t* ph = g_hi + (size_t)row * 128;
    uint32_t* pl = g_lo + (size_t)row * 128;
#pragma unroll
    for (int i = 0; i < 2; i++) {
        // this thread's quad: elements 4*(lane+32i) .. +3 -> pairs q0, q0+1
        int q0 = 2 * (lane + 32 * i);
#pragma unroll
        for (int pp = 0; pp < 2; pp++) {
            int q = q0 + pp;
            float y0 = (v[i * 4 + 2 * pp + 0] - mean) * scale;
            float y1 = (v[i * 4 + 2 * pp + 1] - mean) * scale;
            __half h0 = __float2half_rn(y0);
            __half h1 = __float2half_rn(y1);
            __half l0 = __float2half_rn(y0 - __half2float(h0));
            __half l1 = __float2half_rn(y1 - __half2float(h1));
            // permuted position
            int c = q >> 4;
            int qq = q & 15;
            int ks = qq >> 3;
            int hs = (qq >> 2) & 1;
            int tg = qq & 3;
            int upos = c * 16 + 2 * (ks * 4 + tg) + hs;
            __half2 hh = __halves2half2(h0, h1);
            __half2 ll = __halves2half2(l0, l1);
            ph[upos] = *(uint32_t*)&hh;
            pl[upos] = *(uint32_t*)&ll;
        }
    }
}

// ---------------- kernel 2: fp16x2 mma.m16n8k16 GEMM, upper tiles + mirror ------
#define BM 128
#define BN 128
#define BK 32
#define NKB (LL / BK)                    // 8
#define NTILE (NN / BM)                  // 32
#define NUPPER (NTILE * (NTILE + 1) / 2) // 528
#define TSTRIDE 132
// per-stage layout: A_hi[128][64B] | A_lo | B_hi | B_lo  (8 KB each, 32 KB/stage)
#define TILE_B 8192
#define STAGE_B 32768
#define SMEM_TOT 69632                   // >= max(2*STAGE_B, 128*132*4)

__device__ __forceinline__ void mma_f16(float* d,
                                        uint32_t a0, uint32_t a1, uint32_t a2, uint32_t a3,
                                        uint32_t b0, uint32_t b1) {
    asm volatile(
        "mma.sync.aligned.m16n8k16.row.col.f32.f16.f16.f32 "
        "{%0,%1,%2,%3}, {%4,%5,%6,%7}, {%8,%9}, {%0,%1,%2,%3};"
        : "+f"(d[0]), "+f"(d[1]), "+f"(d[2]), "+f"(d[3])
        : "r"(a0), "r"(a1), "r"(a2), "r"(a3), "r"(b0), "r"(b1));
}

#define CPA16(dst32, src) \
    asm volatile("cp.async.cg.shared.global [%0], [%1], 16;\n" :: "r"(dst32), "l"(src))

__global__ __launch_bounds__(256, 2) void kgemm() {
    extern __shared__ char smem[];

    // map linear tile id -> (ti, tj) upper triangular (tj >= ti)
    int t = blockIdx.x;
    int ti = 0;
    while (t >= NTILE - ti) { t -= NTILE - ti; ti++; }
    int tj = ti + t;

    int b = blockIdx.z;
    int tileM = ti * BM;
    int tileN = tj * BN;
    const uint32_t* __restrict__ Ph = g_hi + (size_t)b * NN * 128;
    const uint32_t* __restrict__ Pl = g_lo + (size_t)b * NN * 128;
    float* __restrict__ C = g_sim + (size_t)b * NN * NN;

    int tid = threadIdx.x;
    int wid = tid >> 5;
    int lane = tid & 31;
    int g = lane >> 2;        // 0..7
    int tg = lane & 3;        // 0..3
    int pg = (g >> 1) & 1;    // parity-rotation for this lane's rows
    int m0w = (wid & 1) * 64;
    int n0w = (wid >> 1) * 32;

    // loader mapping: 256 threads -> 128 rows x 2 halves (2 x 16B groups each)
    int lr = tid >> 1;
    int lh = tid & 1;
    int rot = 2 * ((lr >> 1) & 1);                     // group rotation by row parity
    uint32_t sbase = (uint32_t)__cvta_generic_to_shared(smem);

    float acc[4][4][4];
#pragma unroll
    for (int i = 0; i < 4; i++)
#pragma unroll
        for (int j = 0; j < 4; j++)
#pragma unroll
            for (int q = 0; q < 4; q++) acc[i][j][q] = 0.f;

    // prologue: load chunk 0 into stage 0
    {
        const uint32_t* srcs[4] = {
            Ph + (size_t)(tileM + lr) * 128, Pl + (size_t)(tileM + lr) * 128,
            Ph + (size_t)(tileN + lr) * 128, Pl + (size_t)(tileN + lr) * 128 };
#pragma unroll
        for (int tt = 0; tt < 4; tt++) {
            uint32_t dbase = sbase + tt * TILE_B + lr * 64;
#pragma unroll
            for (int gg2 = 0; gg2 < 2; gg2++) {
                int gg = 2 * lh + gg2;
                CPA16(dbase + (((gg + rot) & 3) * 16), srcs[tt] + gg * 4);
            }
        }
        asm volatile("cp.async.commit_group;");
        asm volatile("cp.async.wait_group 0;");
        __syncthreads();
    }

    for (int kb = 0; kb < NKB; kb++) {
        int buf = kb & 1;
        if (kb + 1 < NKB) {
            int c = kb + 1;
            const uint32_t* srcs[4] = {
                Ph + (size_t)(tileM + lr) * 128 + c * 16,
                Pl + (size_t)(tileM + lr) * 128 + c * 16,
                Ph + (size_t)(tileN + lr) * 128 + c * 16,
                Pl + (size_t)(tileN + lr) * 128 + c * 16 };
            uint32_t st = sbase + (buf ^ 1) * STAGE_B;
#pragma unroll
            for (int tt = 0; tt < 4; tt++) {
                uint32_t dbase = st + tt * TILE_B + lr * 64;
#pragma unroll
                for (int gg2 = 0; gg2 < 2; gg2++) {
                    int gg = 2 * lh + gg2;
                    CPA16(dbase + (((gg + rot) & 3) * 16), srcs[tt] + gg * 4);
                }
            }
            asm volatile("cp.async.commit_group;");
        }

        const char* sbuf = smem + buf * STAGE_B;
#pragma unroll
        for (int ks = 0; ks < 2; ks++) {
            int dq = ((ks << 2) + tg + (pg << 2)) & 7;
            uint2 AH0[4], AH1[4], AL0[4], AL1[4];
#pragma unroll
            for (int i = 0; i < 4; i++) {
                const char* a0p = sbuf + (m0w + 16 * i + g) * 64 + dq * 8;
                AH0[i] = *(const uint2*)(a0p);
                AH1[i] = *(const uint2*)(a0p + 8 * 64);
                AL0[i] = *(const uint2*)(a0p + TILE_B);
                AL1[i] = *(const uint2*)(a0p + TILE_B + 8 * 64);
            }
#pragma unroll
            for (int j = 0; j < 4; j++) {
                const char* bp = sbuf + 2 * TILE_B + (n0w + 8 * j + g) * 64 + dq * 8;
                uint2 BH = *(const uint2*)(bp);
                uint2 BL = *(const uint2*)(bp + TILE_B);
#pragma unroll
                for (int i = 0; i < 4; i++) {
                    mma_f16(acc[i][j], AH0[i].x, AH1[i].x, AH0[i].y, AH1[i].y, BH.x, BH.y);
                    mma_f16(acc[i][j], AH0[i].x, AH1[i].x, AH0[i].y, AH1[i].y, BL.x, BL.y);
                    mma_f16(acc[i][j], AL0[i].x, AL1[i].x, AL0[i].y, AL1[i].y, BH.x, BH.y);
                }
            }
        }

        if (kb + 1 < NKB) {
            asm volatile("cp.async.wait_group 0;");
            __syncthreads();
        }
    }

    // epilogue: scale, relu, zero-diag, store
    const float inv_l = 1.f / LL;
#pragma unroll
    for (int i = 0; i < 4; i++) {
        int gm0 = tileM + m0w + i * 16 + g;
        int gm1 = gm0 + 8;
#pragma unroll
        for (int j = 0; j < 4; j++) {
            int gn = tileN + n0w + j * 8 + 2 * tg;
            float v0 = fmaxf(acc[i][j][0] * inv_l, 0.f);
            float v1 = fmaxf(acc[i][j][1] * inv_l, 0.f);
            float v2 = fmaxf(acc[i][j][2] * inv_l, 0.f);
            float v3 = fmaxf(acc[i][j][3] * inv_l, 0.f);
            if (gm0 == gn)     v0 = 0.f;
            if (gm0 == gn + 1) v1 = 0.f;
            if (gm1 == gn)     v2 = 0.f;
            if (gm1 == gn + 1) v3 = 0.f;
            acc[i][j][0] = v0; acc[i][j][1] = v1;
            acc[i][j][2] = v2; acc[i][j][3] = v3;
            float2 r0 = {v0, v1}, r1 = {v2, v3};
            *(float2*)(C + (size_t)gm0 * NN + gn) = r0;
            *(float2*)(C + (size_t)gm1 * NN + gn) = r1;
        }
    }

    // mirror tile via smem transpose (off-diagonal only)
    if (ti != tj) {
        float* stg = (float*)smem;
        __syncthreads();   // everyone done with stage buffers
#pragma unroll
        for (int i = 0; i < 4; i++) {
            int ml0 = m0w + i * 16 + g;
            int ml1 = ml0 + 8;
#pragma unroll
            for (int j = 0; j < 4; j++) {
                int nl = n0w + j * 8 + 2 * tg;
                stg[(nl)     * TSTRIDE + ml0] = acc[i][j][0];
                stg[(nl + 1) * TSTRIDE + ml0] = acc[i][j][1];
                stg[(nl)     * TSTRIDE + ml1] = acc[i][j][2];
                stg[(nl + 1) * TSTRIDE + ml1] = acc[i][j][3];
            }
        }
        __syncthreads();
#pragma unroll
        for (int it = 0; it < 16; it++) {
            int idx = it * 256 + tid;
            int rr = idx >> 5;
            int c4 = idx & 31;
            float4 v = *(const float4*)&stg[rr * TSTRIDE + c4 * 4];
            *(float4*)(C + (size_t)(tileN + rr) * NN + tileM + c4 * 4) = v;
        }
    }
}

// ---------------- kernel 3: fused-load tournament top-20 + normalize ------------
#define TPB3 128
__global__ __launch_bounds__(TPB3) void ktopk(float* __restrict__ out) {
    int b = blockIdx.y;
    int row = blockIdx.x;
    const float* simrow = g_sim + ((size_t)b * NN + row) * NN;
    float* orow = out + ((size_t)b * NN + row) * NN;
    const uint32_t* mbits = g_maskbits + b * (NN / 32);

    __shared__ float sv[NN];
    __shared__ float cv[TPB3];
    __shared__ int   ci[TPB3];
    __shared__ float sel_v[KSEL];
    __shared__ int   sel_i[KSEL];
    __shared__ float fscale;

    int tid = threadIdx.x;
    int lane = tid & 31;

    {
        float bv = -INFINITY; int bi = 0x7fffffff;
#pragma unroll
        for (int j = 0; j < 8; j++) {
            int i = tid * 4 + 512 * j;
            float4 v = *(const float4*)(simrow + i);
            uint32_t mb = (mbits[i >> 5] >> (i & 31)) & 0xFu;
            if (!(mb & 1u)) v.x = -FLT_MAX;
            if (!(mb & 2u)) v.y = -FLT_MAX;
            if (!(mb & 4u)) v.z = -FLT_MAX;
            if (!(mb & 8u)) v.w = -FLT_MAX;
            *(float4*)(sv + i) = v;
            if (v.x > bv) { bv = v.x; bi = i; }
            if (v.y > bv) { bv = v.y; bi = i + 1; }
            if (v.z > bv) { bv = v.z; bi = i + 2; }
            if (v.w > bv) { bv = v.w; bi = i + 3; }
        }
        cv[tid] = bv; ci[tid] = bi;
    }
    __syncthreads();

    if (tid < 32) {
        for (int it = 0; it < KSEL; it++) {
            float bv = cv[lane]; int bi = ci[lane];
#pragma unroll
            for (int t2 = 1; t2 < 4; t2++) {
                float v = cv[lane + 32 * t2]; int i2 = ci[lane + 32 * t2];
                if (v > bv || (v == bv && i2 < bi)) { bv = v; bi = i2; }
            }
#pragma unroll
            for (int off = 16; off; off >>= 1) {
                float ov = __shfl_xor_sync(0xffffffffu, bv, off);
                int   oi = __shfl_xor_sync(0xffffffffu, bi, off);
                if (ov > bv || (ov == bv && oi < bi)) { bv = ov; bi = oi; }
            }
            if (lane == 0) {
                sel_v[it] = bv;
                sel_i[it] = bi;
                sv[bi] = -INFINITY;
            }
            __syncwarp();
            int c = (bi >> 2) & (TPB3 - 1);
            int idx = 4 * c + 512 * (lane >> 2) + (lane & 3);
            float nv = sv[idx]; int ni = idx;
#pragma unroll
            for (int off = 16; off; off >>= 1) {
                float ov = __shfl_xor_sync(0xffffffffu, nv, off);
                int   oi = __shfl_xor_sync(0xffffffffu, ni, off);
                if (ov > nv || (ov == nv && oi < ni)) { nv = ov; ni = oi; }
            }
            if (lane == 0) { cv[c] = nv; ci[c] = ni; }
            __syncwarp();
        }
        if (lane == 0) {
            float S = 0.f;
#pragma unroll
            for (int t2 = 0; t2 < KSEL; t2++) {
                float v = sel_v[t2];
                if (v < 0.f) v = 0.f;
                if (sel_i[t2] == row) v = 0.f;
                sel_v[t2] = v;
                S += v;
            }
            float r1 = 1.f / fmaxf(S, EPSF);
            float S1 = S * r1;
            float r2 = 1.f / fmaxf(S1, EPSF);
            fscale = r1 * r2;
        }
    }
    __syncthreads();

    float4 z = {0.f, 0.f, 0.f, 0.f};
#pragma unroll
    for (int j = 0; j < 8; j++)
        *(float4*)(orow + tid * 4 + 512 * j) = z;
    __syncthreads();
    if (tid < KSEL) orow[sel_i[tid]] = sel_v[tid] * fscale;
}

// ---------------- launch ----------------
extern "C" void kernel_launch(void* const* d_in, const int* in_sizes, int n_in,
                              void* d_out, int out_size) {
    const float* hist = (const float*)d_in[0];
    const int* mask = (const int*)d_in[1];
    float* out = (float*)d_out;

    static int smem_set = 0;
    if (!smem_set) {
        cudaFuncSetAttribute(kgemm, cudaFuncAttributeMaxDynamicSharedMemorySize, SMEM_TOT);
        smem_set = 1;
    }

    kmask<<<BB, NN / 32>>>(mask);
    knorm<<<(BB * NN) / 4, 128>>>(hist, mask);

    dim3 g2(NUPPER, 1, BB);
    kgemm<<<g2, 256, SMEM_TOT>>>();

    dim3 g3(NN, BB);
    ktopk<<<g3, TPB3>>>(out);
}